// round 2
// baseline (speedup 1.0000x reference)
#include <cuda_runtime.h>
#include <math.h>

// ---------------- problem constants ----------------
#define DIMC   256          // model dim
#define SPAT   4096         // 64*64
#define NHEAD  8
#define HDIM   32
#define HIDM   53           // int(32*1.66)
#define MAXB   16

// ---------------- device scratch (no cudaMalloc allowed) ----------------
__device__ float g_mean[MAXB * DIMC];          // per (b,c) spatial mean
__device__ float g_bb[MAXB * 512];             // adjusted bias for [fc1;fcv]
__device__ float g_wcat[512 * DIMC];           // [w_fc1; w_fcv]
__device__ float g_xv[(size_t)MAXB * 512 * SPAT];   // rows 0..255 = x1, 256..511 = value
__device__ float g_x2[(size_t)MAXB * DIMC * SPAT];  // clustering output (unfolded)

// ---------------- packed f32x2 FMA ----------------
__device__ __forceinline__ void ffma2(unsigned long long &d, unsigned long long a, unsigned long long b) {
    asm("fma.rn.f32x2 %0, %1, %2, %0;" : "+l"(d) : "l"(a), "l"(b));
}

// ---------------- kernel 1: spatial mean ----------------
__global__ void mean_kernel(const float* __restrict__ x, float* __restrict__ meanOut) {
    int bc = blockIdx.x;                      // B*256 blocks
    const float* p = x + (size_t)bc * SPAT;
    float s = 0.f;
    for (int i = threadIdx.x; i < SPAT; i += 256) s += p[i];
    __shared__ float red[256];
    red[threadIdx.x] = s;
    __syncthreads();
    for (int off = 128; off > 0; off >>= 1) {
        if (threadIdx.x < off) red[threadIdx.x] += red[threadIdx.x + off];
        __syncthreads();
    }
    if (threadIdx.x == 0) meanOut[bc] = red[0] * (1.f / (float)SPAT);
}

// ---------------- kernel 2a: concat weights ----------------
__global__ void wcat_kernel(const float* __restrict__ w1, const float* __restrict__ wv) {
    int i = blockIdx.x * blockDim.x + threadIdx.x;
    if (i < 65536) g_wcat[i] = w1[i];
    else if (i < 131072) g_wcat[i] = wv[i - 65536];
}

// ---------------- kernel 2b: adjusted bias bb[b, r] ----------------
__global__ void bias_kernel(const float* __restrict__ w1, const float* __restrict__ b1,
                            const float* __restrict__ wv, const float* __restrict__ bv,
                            const float* __restrict__ scaler, int B) {
    int id = blockIdx.x * blockDim.x + threadIdx.x;
    if (id >= B * 512) return;
    int b = id >> 9, r = id & 511;
    const float* w = (r < 256) ? (w1 + (size_t)r * DIMC) : (wv + (size_t)(r - 256) * DIMC);
    float base = (r < 256) ? b1[r] : bv[r - 256];
    const float* mn = g_mean + b * DIMC;
    float s = 0.f;
#pragma unroll 8
    for (int c = 0; c < DIMC; c++) s += w[c] * scaler[c] * mn[c];
    g_bb[id] = base + s;
}

// ---------------- kernel 3/5: SGEMM with f32x2 ----------------
// C[b, m, n] = sum_k W[m,k] * X[b,k,n] + bias
// BM=128, BN=128, BK=8, 256 threads, 8x8 per thread.
// Thread's 8 columns: {tx+16j} and {tx+64+16j}, j=0..3, packed as f32x2 pairs.
#define BM 128
#define BN 128
#define BKK 8

__global__ __launch_bounds__(256, 2)
void sgemm_kernel(const float* __restrict__ W,     // [M, K] row-major
                  const float* __restrict__ X,     // [B, K, S]
                  const float* __restrict__ bias,  // [M] or [B, M]
                  float* __restrict__ O,           // [B, M, S]
                  int M, int K, int S, int biasPerBatch) {
    const int b  = blockIdx.z;
    const int n0 = blockIdx.x * BN;
    const int m0 = blockIdx.y * BM;
    const int tid = threadIdx.x;
    const int tx = tid & 15;
    const int ty = tid >> 4;

    __shared__ __align__(16) float2 As[2][BKK][BM];      // (v,v) duplicated pairs
    __shared__ __align__(16) float2 Bs[2][BKK][BN / 2];  // (col j, col j+64)

    const float* Xb = X + (size_t)b * K * S;

    const int a_row = tid >> 1;
    const int a_kp  = (tid & 1) * 4;
    const int b_kr  = tid >> 5;
    const int b_c4  = (tid & 31) * 4;

    unsigned long long acc[8][4];
#pragma unroll
    for (int i = 0; i < 8; i++)
#pragma unroll
        for (int j = 0; j < 4; j++) acc[i][j] = 0ull;

    // ---- tile loaders ----
    auto loadA = [&](int buf, int k0) {
        float4 v = *reinterpret_cast<const float4*>(W + (size_t)(m0 + a_row) * K + k0 + a_kp);
        As[buf][a_kp + 0][a_row] = make_float2(v.x, v.x);
        As[buf][a_kp + 1][a_row] = make_float2(v.y, v.y);
        As[buf][a_kp + 2][a_row] = make_float2(v.z, v.z);
        As[buf][a_kp + 3][a_row] = make_float2(v.w, v.w);
    };
    auto loadB = [&](int buf, int k0) {
        float4 v = *reinterpret_cast<const float4*>(Xb + (size_t)(k0 + b_kr) * S + n0 + b_c4);
        float vv[4] = {v.x, v.y, v.z, v.w};
#pragma unroll
        for (int i = 0; i < 4; i++) {
            int cc = b_c4 + i;
            if (cc < 64) Bs[buf][b_kr][cc].x = vv[i];
            else         Bs[buf][b_kr][cc - 64].y = vv[i];
        }
    };

    loadA(0, 0);
    loadB(0, 0);
    __syncthreads();

    int buf = 0;
    for (int kt = 0; kt < K; kt += BKK) {
        if (kt + BKK < K) { loadA(buf ^ 1, kt + BKK); loadB(buf ^ 1, kt + BKK); }
#pragma unroll
        for (int k = 0; k < BKK; k++) {
            ulonglong2 a01 = *reinterpret_cast<const ulonglong2*>(&As[buf][k][ty * 8 + 0]);
            ulonglong2 a23 = *reinterpret_cast<const ulonglong2*>(&As[buf][k][ty * 8 + 2]);
            ulonglong2 a45 = *reinterpret_cast<const ulonglong2*>(&As[buf][k][ty * 8 + 4]);
            ulonglong2 a67 = *reinterpret_cast<const ulonglong2*>(&As[buf][k][ty * 8 + 6]);
            unsigned long long aa[8] = {a01.x, a01.y, a23.x, a23.y, a45.x, a45.y, a67.x, a67.y};
            unsigned long long bb4[4];
#pragma unroll
            for (int j = 0; j < 4; j++)
                bb4[j] = *reinterpret_cast<const unsigned long long*>(&Bs[buf][k][tx + 16 * j]);
#pragma unroll
            for (int i = 0; i < 8; i++)
#pragma unroll
                for (int j = 0; j < 4; j++)
                    ffma2(acc[i][j], aa[i], bb4[j]);
        }
        __syncthreads();
        buf ^= 1;
    }

    // ---- epilogue ----
#pragma unroll
    for (int i = 0; i < 8; i++) {
        int row = m0 + ty * 8 + i;
        float bvv = bias[(biasPerBatch ? b * M : 0) + row];
        float* orow = O + ((size_t)b * M + row) * S + n0;
#pragma unroll
        for (int j = 0; j < 4; j++) {
            float lo = __uint_as_float((unsigned)(acc[i][j] & 0xffffffffull));
            float hi = __uint_as_float((unsigned)(acc[i][j] >> 32));
            orow[tx + 16 * j]      = lo + bvv;
            orow[64 + tx + 16 * j] = hi + bvv;
        }
    }
}

// ---------------- kernel 4: clustering (one block per fold window) ----------------
// Window: 32 channels x 32x32 tokens. M=4 clusters, N=1024 tokens.
__global__ __launch_bounds__(256)
void cluster_kernel(const float* __restrict__ w1, const float* __restrict__ bb1,
                    const float* __restrict__ w2, const float* __restrict__ bb2,
                    const float* __restrict__ alphaP, const float* __restrict__ betaP) {
    const int tid = threadIdx.x;
    const int bbk = blockIdx.x;                 // = bh*4 + fi*2 + fj
    const int bh = bbk >> 2;
    const int fi = (bbk >> 1) & 1;
    const int fj = bbk & 1;
    const int batch = bh >> 3;
    const int head = bh & 7;

    const size_t foldoff = (size_t)fi * 32 * 64 + (size_t)fj * 32;
    const float* xbase = g_xv + ((size_t)batch * 512 + head * HDIM) * SPAT + foldoff;
    const float* vbase = xbase + (size_t)256 * SPAT;
    float* obase = g_x2 + ((size_t)batch * DIMC + head * HDIM) * SPAT + foldoff;

    __shared__ float a8[2048];        // [c][pos]  pos=pi*8+pj; reused as MLP output o8
    __shared__ float hbuf[HIDM * 64]; // [j][p]
    __shared__ float w1s[HIDM * HDIM], b1s[HIDM], w2s[HDIM * HIDM], b2s[HDIM];
    __shared__ float ctrs[128], vcs[128], cns[128], outm[128], accs[128], cavg[128];
    __shared__ float cnorm[4], cnt[4];
    __shared__ float simval[1024];
    __shared__ unsigned char mstar[1024];

    // load MLP weights
    for (int i = tid; i < HIDM * HDIM; i += 256) { w1s[i] = w1[i]; w2s[i] = w2[i]; }
    if (tid < HIDM) b1s[tid] = bb1[tid];
    if (tid < HDIM) b2s[tid] = bb2[tid];

    // ---- centers pipeline: pass 0 = value, pass 1 = x ----
    for (int pass = 0; pass < 2; pass++) {
        const float* src = (pass == 0) ? vbase : xbase;
        float* dst = (pass == 0) ? vcs : ctrs;
        __syncthreads();
        // avg-pool 32x32 -> 8x8 per channel
#pragma unroll
        for (int rep = 0; rep < 8; rep++) {
            int e = rep * 256 + tid;
            int c = e >> 6, pos = e & 63, pi = pos >> 3, pj = pos & 7;
            const float* pc = src + (size_t)c * SPAT;
            float s = 0.f;
#pragma unroll
            for (int u = 0; u < 4; u++)
#pragma unroll
                for (int v2 = 0; v2 < 4; v2++)
                    s += pc[(pi * 4 + u) * 64 + pj * 4 + v2];
            a8[c * 64 + pos] = s * (1.f / 16.f);
        }
        __syncthreads();
        // centers avg part (avg of a8 over 4x4 groups)  — reads a8 only
        if (tid < 128) {
            int m = tid >> 5, c = tid & 31, qi = m >> 1, qj = m & 1;
            float s = 0.f;
#pragma unroll
            for (int u = 0; u < 4; u++)
#pragma unroll
                for (int v2 = 0; v2 < 4; v2++)
                    s += a8[c * 64 + (qi * 4 + u) * 8 + qj * 4 + v2];
            cavg[tid] = s * (1.f / 16.f);
        }
        // MLP layer 1 (reads a8, writes hbuf), exact GELU
        for (int eh = tid; eh < HIDM * 64; eh += 256) {
            int j = eh >> 6, p = eh & 63;
            float s = b1s[j];
#pragma unroll
            for (int c = 0; c < HDIM; c++) s += w1s[j * HDIM + c] * a8[c * 64 + p];
            hbuf[eh] = 0.5f * s * (1.f + erff(s * 0.70710678118654752440f));
        }
        __syncthreads();
        // MLP layer 2 -> o8 stored into a8 (a8 dead now)
        for (int eo = tid; eo < 2048; eo += 256) {
            int c = eo >> 6, p = eo & 63;
            float s = b2s[c];
#pragma unroll
            for (int j = 0; j < HIDM; j++) s += w2s[c * HIDM + j] * hbuf[j * 64 + p];
            a8[eo] = s;
        }
        __syncthreads();
        // max-pool 8x8 -> 2x2 and add
        if (tid < 128) {
            int m = tid >> 5, c = tid & 31, qi = m >> 1, qj = m & 1;
            float mx = -INFINITY;
#pragma unroll
            for (int u = 0; u < 4; u++)
#pragma unroll
                for (int v2 = 0; v2 < 4; v2++)
                    mx = fmaxf(mx, a8[c * 64 + (qi * 4 + u) * 8 + qj * 4 + v2]);
            dst[tid] = cavg[tid] + mx;
        }
        __syncthreads();
    }

    // ---- l2norm of centers ----
    if (tid < 4) {
        float s = 0.f;
#pragma unroll
        for (int c = 0; c < HDIM; c++) { float v = ctrs[tid * 32 + c]; s += v * v; }
        cnorm[tid] = fmaxf(sqrtf(s), 1e-12f);
    }
    __syncthreads();
    if (tid < 128) cns[tid] = ctrs[tid] / cnorm[tid >> 5];
    __syncthreads();

    const float alpha = alphaP[0], beta = betaP[0];

    // ---- sim + argmax per token ----
#pragma unroll
    for (int rep = 0; rep < 4; rep++) {
        int n = rep * 256 + tid;
        int wi = n >> 5, hj = n & 31;
        const float* px = xbase + wi * 64 + hj;
        float xt[32];
        float ss = 0.f;
#pragma unroll
        for (int c = 0; c < HDIM; c++) { float v = px[c * SPAT]; xt[c] = v; ss += v * v; }
        float inv = 1.f / fmaxf(sqrtf(ss), 1e-12f);
        float best = -1.f; int bm = 0;
#pragma unroll
        for (int m = 0; m < 4; m++) {
            float d = 0.f;
#pragma unroll
            for (int c = 0; c < HDIM; c++) d += cns[m * 32 + c] * xt[c];
            d *= inv;
            float sg = 1.f / (1.f + expf(-(beta + alpha * d)));
            if (sg > best) { best = sg; bm = m; }   // first-max wins (strict >)
        }
        simval[n] = best;
        mstar[n] = (unsigned char)bm;
    }
    __syncthreads();

    // ---- combine: acc[m][c] = sum_n masked sim * v ----
    {
        int warp = tid >> 5, lane = tid & 31;
#pragma unroll
        for (int cc = 0; cc < 4; cc++) {
            int c = warp * 4 + cc;
            const float* pv = vbase + (size_t)c * SPAT;
            float am0 = 0.f, am1 = 0.f, am2 = 0.f, am3 = 0.f;
            for (int q = 0; q < 32; q++) {
                int n = q * 32 + lane;
                float t2 = simval[n] * pv[q * 64 + lane];
                int m = mstar[n];
                am0 += (m == 0) ? t2 : 0.f;
                am1 += (m == 1) ? t2 : 0.f;
                am2 += (m == 2) ? t2 : 0.f;
                am3 += (m == 3) ? t2 : 0.f;
            }
            float am[4] = {am0, am1, am2, am3};
#pragma unroll
            for (int m = 0; m < 4; m++) {
                float s = am[m];
                for (int o = 16; o; o >>= 1) s += __shfl_down_sync(0xffffffffu, s, o);
                if (lane == 0) accs[m * 32 + c] = s;
            }
        }
        if (warp == 0) {
            float pc4[4] = {0.f, 0.f, 0.f, 0.f};
            for (int q = 0; q < 32; q++) pc4[mstar[q * 32 + lane]] += 1.f;
#pragma unroll
            for (int m = 0; m < 4; m++) {
                float s = pc4[m];
                for (int o = 16; o; o >>= 1) s += __shfl_down_sync(0xffffffffu, s, o);
                if (lane == 0) cnt[m] = s;
            }
        }
    }
    __syncthreads();
    if (tid < 128) outm[tid] = (accs[tid] + vcs[tid]) / (cnt[tid >> 5] + 1.f);
    __syncthreads();

    // ---- dispatch: token_out[n][c] = outm[m*][c] * sim[n]; write unfolded ----
    for (int idx = tid; idx < 32 * 1024; idx += 256) {
        int c = idx >> 10, n = idx & 1023;
        int wi = n >> 5, hj = n & 31;
        obase[(size_t)c * SPAT + wi * 64 + hj] = outm[mstar[n] * 32 + c] * simval[n];
    }
}

// ---------------- launcher ----------------
extern "C" void kernel_launch(void* const* d_in, const int* in_sizes, int n_in,
                              void* d_out, int out_size) {
    const float* x       = (const float*)d_in[0];
    const float* scaler  = (const float*)d_in[1];
    const float* w_fc1   = (const float*)d_in[2];
    const float* b_fc1   = (const float*)d_in[3];
    const float* w_fcv   = (const float*)d_in[4];
    const float* b_fcv   = (const float*)d_in[5];
    const float* w_fc2   = (const float*)d_in[6];
    const float* b_fc2   = (const float*)d_in[7];
    const float* alpha   = (const float*)d_in[8];
    const float* beta    = (const float*)d_in[9];
    const float* off_w1  = (const float*)d_in[10];
    const float* off_b1  = (const float*)d_in[11];
    const float* off_w2  = (const float*)d_in[12];
    const float* off_b2  = (const float*)d_in[13];
    float* out = (float*)d_out;

    int B = in_sizes[0] / (DIMC * SPAT);
    if (B > MAXB) B = MAXB;

    // device scratch pointers
    float *p_mean, *p_bb, *p_wcat, *p_xv, *p_x2;
    cudaGetSymbolAddress((void**)&p_mean, g_mean);
    cudaGetSymbolAddress((void**)&p_bb,   g_bb);
    cudaGetSymbolAddress((void**)&p_wcat, g_wcat);
    cudaGetSymbolAddress((void**)&p_xv,   g_xv);
    cudaGetSymbolAddress((void**)&p_x2,   g_x2);

    // 1. spatial means
    mean_kernel<<<B * DIMC, 256>>>(x, p_mean);
    // 2. weight concat + adjusted bias
    wcat_kernel<<<512, 256>>>(w_fc1, w_fcv);
    bias_kernel<<<(B * 512 + 255) / 256, 256>>>(w_fc1, b_fc1, w_fcv, b_fcv, scaler, B);
    // 3. fused fc1+fcv GEMM on raw x (gap correction folded into bias)
    {
        dim3 grid(SPAT / BN, 512 / BM, B);
        sgemm_kernel<<<grid, 256>>>(p_wcat, x, p_bb, p_xv, 512, DIMC, SPAT, 1);
    }
    // 4. clustering per fold window
    cluster_kernel<<<B * 32, 256>>>(off_w1, off_b1, off_w2, off_b2, alpha, beta);
    // 5. fc2 GEMM -> output
    {
        dim3 grid(SPAT / BN, DIMC / BM, B);
        sgemm_kernel<<<grid, 256>>>(w_fc2, p_x2, b_fc2, out, DIMC, DIMC, SPAT, 0);
    }
}

// round 3
// speedup vs baseline: 1.0001x; 1.0001x over previous
#include <cuda_runtime.h>
#include <math.h>

// ---------------- problem constants ----------------
#define DIMC   256          // model dim
#define SPAT   4096         // 64*64
#define NHEAD  8
#define HDIM   32
#define HIDM   53           // int(32*1.66)
#define MAXB   16

// ---------------- device scratch (no cudaMalloc allowed) ----------------
__device__ float g_mean[MAXB * DIMC];          // per (b,c) spatial mean
__device__ float g_bb[MAXB * 512];             // adjusted bias for [fc1;fcv]
__device__ float g_wcat[512 * DIMC];           // [w_fc1; w_fcv]
__device__ float g_xv[(size_t)MAXB * 512 * SPAT];   // rows 0..255 = x1, 256..511 = value
__device__ float g_x2[(size_t)MAXB * DIMC * SPAT];  // clustering output (unfolded)

// ---------------- packed f32x2 FMA ----------------
__device__ __forceinline__ void ffma2(unsigned long long &d, unsigned long long a, unsigned long long b) {
    asm("fma.rn.f32x2 %0, %1, %2, %0;" : "+l"(d) : "l"(a), "l"(b));
}

// ---------------- kernel 1: spatial mean ----------------
__global__ void mean_kernel(const float* __restrict__ x, float* __restrict__ meanOut) {
    int bc = blockIdx.x;                      // B*256 blocks
    const float* p = x + (size_t)bc * SPAT;
    float s = 0.f;
    for (int i = threadIdx.x; i < SPAT; i += 256) s += p[i];
    __shared__ float red[256];
    red[threadIdx.x] = s;
    __syncthreads();
    for (int off = 128; off > 0; off >>= 1) {
        if (threadIdx.x < off) red[threadIdx.x] += red[threadIdx.x + off];
        __syncthreads();
    }
    if (threadIdx.x == 0) meanOut[bc] = red[0] * (1.f / (float)SPAT);
}

// ---------------- kernel 2a: concat weights ----------------
__global__ void wcat_kernel(const float* __restrict__ w1, const float* __restrict__ wv) {
    int i = blockIdx.x * blockDim.x + threadIdx.x;
    if (i < 65536) g_wcat[i] = w1[i];
    else if (i < 131072) g_wcat[i] = wv[i - 65536];
}

// ---------------- kernel 2b: adjusted bias bb[b, r] ----------------
__global__ void bias_kernel(const float* __restrict__ w1, const float* __restrict__ b1,
                            const float* __restrict__ wv, const float* __restrict__ bv,
                            const float* __restrict__ scaler, int B) {
    int id = blockIdx.x * blockDim.x + threadIdx.x;
    if (id >= B * 512) return;
    int b = id >> 9, r = id & 511;
    const float* w = (r < 256) ? (w1 + (size_t)r * DIMC) : (wv + (size_t)(r - 256) * DIMC);
    float base = (r < 256) ? b1[r] : bv[r - 256];
    const float* mn = g_mean + b * DIMC;
    float s = 0.f;
#pragma unroll 8
    for (int c = 0; c < DIMC; c++) s += w[c] * scaler[c] * mn[c];
    g_bb[id] = base + s;
}

// ---------------- kernel 3/5: SGEMM with f32x2 ----------------
// C[b, m, n] = sum_k W[m,k] * X[b,k,n] + bias
// BM=128, BN=128, BK=8, 256 threads, 8x8 per thread.
// Thread's 8 columns: {tx+16j} and {tx+64+16j}, j=0..3, packed as f32x2 pairs.
#define BM 128
#define BN 128
#define BKK 8

__global__ __launch_bounds__(256, 2)
void sgemm_kernel(const float* __restrict__ W,     // [M, K] row-major
                  const float* __restrict__ X,     // [B, K, S]
                  const float* __restrict__ bias,  // [M] or [B, M]
                  float* __restrict__ O,           // [B, M, S]
                  int M, int K, int S, int biasPerBatch) {
    const int b  = blockIdx.z;
    const int n0 = blockIdx.x * BN;
    const int m0 = blockIdx.y * BM;
    const int tid = threadIdx.x;
    const int tx = tid & 15;
    const int ty = tid >> 4;

    __shared__ __align__(16) float2 As[2][BKK][BM];      // (v,v) duplicated pairs
    __shared__ __align__(16) float2 Bs[2][BKK][BN / 2];  // (col j, col j+64)

    const float* Xb = X + (size_t)b * K * S;

    const int a_row = tid >> 1;
    const int a_kp  = (tid & 1) * 4;
    const int b_kr  = tid >> 5;
    const int b_c4  = (tid & 31) * 4;

    unsigned long long acc[8][4];
#pragma unroll
    for (int i = 0; i < 8; i++)
#pragma unroll
        for (int j = 0; j < 4; j++) acc[i][j] = 0ull;

    // ---- tile loaders ----
    auto loadA = [&](int buf, int k0) {
        float4 v = *reinterpret_cast<const float4*>(W + (size_t)(m0 + a_row) * K + k0 + a_kp);
        As[buf][a_kp + 0][a_row] = make_float2(v.x, v.x);
        As[buf][a_kp + 1][a_row] = make_float2(v.y, v.y);
        As[buf][a_kp + 2][a_row] = make_float2(v.z, v.z);
        As[buf][a_kp + 3][a_row] = make_float2(v.w, v.w);
    };
    auto loadB = [&](int buf, int k0) {
        float4 v = *reinterpret_cast<const float4*>(Xb + (size_t)(k0 + b_kr) * S + n0 + b_c4);
        float vv[4] = {v.x, v.y, v.z, v.w};
#pragma unroll
        for (int i = 0; i < 4; i++) {
            int cc = b_c4 + i;
            if (cc < 64) Bs[buf][b_kr][cc].x = vv[i];
            else         Bs[buf][b_kr][cc - 64].y = vv[i];
        }
    };

    loadA(0, 0);
    loadB(0, 0);
    __syncthreads();

    int buf = 0;
    for (int kt = 0; kt < K; kt += BKK) {
        if (kt + BKK < K) { loadA(buf ^ 1, kt + BKK); loadB(buf ^ 1, kt + BKK); }
#pragma unroll
        for (int k = 0; k < BKK; k++) {
            ulonglong2 a01 = *reinterpret_cast<const ulonglong2*>(&As[buf][k][ty * 8 + 0]);
            ulonglong2 a23 = *reinterpret_cast<const ulonglong2*>(&As[buf][k][ty * 8 + 2]);
            ulonglong2 a45 = *reinterpret_cast<const ulonglong2*>(&As[buf][k][ty * 8 + 4]);
            ulonglong2 a67 = *reinterpret_cast<const ulonglong2*>(&As[buf][k][ty * 8 + 6]);
            unsigned long long aa[8] = {a01.x, a01.y, a23.x, a23.y, a45.x, a45.y, a67.x, a67.y};
            unsigned long long bb4[4];
#pragma unroll
            for (int j = 0; j < 4; j++)
                bb4[j] = *reinterpret_cast<const unsigned long long*>(&Bs[buf][k][tx + 16 * j]);
#pragma unroll
            for (int i = 0; i < 8; i++)
#pragma unroll
                for (int j = 0; j < 4; j++)
                    ffma2(acc[i][j], aa[i], bb4[j]);
        }
        __syncthreads();
        buf ^= 1;
    }

    // ---- epilogue ----
#pragma unroll
    for (int i = 0; i < 8; i++) {
        int row = m0 + ty * 8 + i;
        float bvv = bias[(biasPerBatch ? b * M : 0) + row];
        float* orow = O + ((size_t)b * M + row) * S + n0;
#pragma unroll
        for (int j = 0; j < 4; j++) {
            float lo = __uint_as_float((unsigned)(acc[i][j] & 0xffffffffull));
            float hi = __uint_as_float((unsigned)(acc[i][j] >> 32));
            orow[tx + 16 * j]      = lo + bvv;
            orow[64 + tx + 16 * j] = hi + bvv;
        }
    }
}

// ---------------- kernel 4: clustering (one block per fold window) ----------------
// Window: 32 channels x 32x32 tokens. M=4 clusters, N=1024 tokens.
__global__ __launch_bounds__(256)
void cluster_kernel(const float* __restrict__ w1, const float* __restrict__ bb1,
                    const float* __restrict__ w2, const float* __restrict__ bb2,
                    const float* __restrict__ alphaP, const float* __restrict__ betaP) {
    const int tid = threadIdx.x;
    const int bbk = blockIdx.x;                 // = bh*4 + fi*2 + fj
    const int bh = bbk >> 2;
    const int fi = (bbk >> 1) & 1;
    const int fj = bbk & 1;
    const int batch = bh >> 3;
    const int head = bh & 7;

    const size_t foldoff = (size_t)fi * 32 * 64 + (size_t)fj * 32;
    const float* xbase = g_xv + ((size_t)batch * 512 + head * HDIM) * SPAT + foldoff;
    const float* vbase = xbase + (size_t)256 * SPAT;
    float* obase = g_x2 + ((size_t)batch * DIMC + head * HDIM) * SPAT + foldoff;

    __shared__ float a8[2048];        // [c][pos]  pos=pi*8+pj; reused as MLP output o8
    __shared__ float hbuf[HIDM * 64]; // [j][p]
    __shared__ float w1s[HIDM * HDIM], b1s[HIDM], w2s[HDIM * HIDM], b2s[HDIM];
    __shared__ float ctrs[128], vcs[128], cns[128], outm[128], accs[128], cavg[128];
    __shared__ float cnorm[4], cnt[4];
    __shared__ float simval[1024];
    __shared__ unsigned char mstar[1024];

    // load MLP weights
    for (int i = tid; i < HIDM * HDIM; i += 256) { w1s[i] = w1[i]; w2s[i] = w2[i]; }
    if (tid < HIDM) b1s[tid] = bb1[tid];
    if (tid < HDIM) b2s[tid] = bb2[tid];

    // ---- centers pipeline: pass 0 = value, pass 1 = x ----
    for (int pass = 0; pass < 2; pass++) {
        const float* src = (pass == 0) ? vbase : xbase;
        float* dst = (pass == 0) ? vcs : ctrs;
        __syncthreads();
        // avg-pool 32x32 -> 8x8 per channel
#pragma unroll
        for (int rep = 0; rep < 8; rep++) {
            int e = rep * 256 + tid;
            int c = e >> 6, pos = e & 63, pi = pos >> 3, pj = pos & 7;
            const float* pc = src + (size_t)c * SPAT;
            float s = 0.f;
#pragma unroll
            for (int u = 0; u < 4; u++)
#pragma unroll
                for (int v2 = 0; v2 < 4; v2++)
                    s += pc[(pi * 4 + u) * 64 + pj * 4 + v2];
            a8[c * 64 + pos] = s * (1.f / 16.f);
        }
        __syncthreads();
        // centers avg part (avg of a8 over 4x4 groups)  — reads a8 only
        if (tid < 128) {
            int m = tid >> 5, c = tid & 31, qi = m >> 1, qj = m & 1;
            float s = 0.f;
#pragma unroll
            for (int u = 0; u < 4; u++)
#pragma unroll
                for (int v2 = 0; v2 < 4; v2++)
                    s += a8[c * 64 + (qi * 4 + u) * 8 + qj * 4 + v2];
            cavg[tid] = s * (1.f / 16.f);
        }
        // MLP layer 1 (reads a8, writes hbuf), exact GELU
        for (int eh = tid; eh < HIDM * 64; eh += 256) {
            int j = eh >> 6, p = eh & 63;
            float s = b1s[j];
#pragma unroll
            for (int c = 0; c < HDIM; c++) s += w1s[j * HDIM + c] * a8[c * 64 + p];
            hbuf[eh] = 0.5f * s * (1.f + erff(s * 0.70710678118654752440f));
        }
        __syncthreads();
        // MLP layer 2 -> o8 stored into a8 (a8 dead now)
        for (int eo = tid; eo < 2048; eo += 256) {
            int c = eo >> 6, p = eo & 63;
            float s = b2s[c];
#pragma unroll
            for (int j = 0; j < HIDM; j++) s += w2s[c * HIDM + j] * hbuf[j * 64 + p];
            a8[eo] = s;
        }
        __syncthreads();
        // max-pool 8x8 -> 2x2 and add
        if (tid < 128) {
            int m = tid >> 5, c = tid & 31, qi = m >> 1, qj = m & 1;
            float mx = -INFINITY;
#pragma unroll
            for (int u = 0; u < 4; u++)
#pragma unroll
                for (int v2 = 0; v2 < 4; v2++)
                    mx = fmaxf(mx, a8[c * 64 + (qi * 4 + u) * 8 + qj * 4 + v2]);
            dst[tid] = cavg[tid] + mx;
        }
        __syncthreads();
    }

    // ---- l2norm of centers ----
    if (tid < 4) {
        float s = 0.f;
#pragma unroll
        for (int c = 0; c < HDIM; c++) { float v = ctrs[tid * 32 + c]; s += v * v; }
        cnorm[tid] = fmaxf(sqrtf(s), 1e-12f);
    }
    __syncthreads();
    if (tid < 128) cns[tid] = ctrs[tid] / cnorm[tid >> 5];
    __syncthreads();

    const float alpha = alphaP[0], beta = betaP[0];

    // ---- sim + argmax per token ----
#pragma unroll
    for (int rep = 0; rep < 4; rep++) {
        int n = rep * 256 + tid;
        int wi = n >> 5, hj = n & 31;
        const float* px = xbase + wi * 64 + hj;
        float xt[32];
        float ss = 0.f;
#pragma unroll
        for (int c = 0; c < HDIM; c++) { float v = px[c * SPAT]; xt[c] = v; ss += v * v; }
        float inv = 1.f / fmaxf(sqrtf(ss), 1e-12f);
        float best = -1.f; int bm = 0;
#pragma unroll
        for (int m = 0; m < 4; m++) {
            float d = 0.f;
#pragma unroll
            for (int c = 0; c < HDIM; c++) d += cns[m * 32 + c] * xt[c];
            d *= inv;
            float sg = 1.f / (1.f + expf(-(beta + alpha * d)));
            if (sg > best) { best = sg; bm = m; }   // first-max wins (strict >)
        }
        simval[n] = best;
        mstar[n] = (unsigned char)bm;
    }
    __syncthreads();

    // ---- combine: acc[m][c] = sum_n masked sim * v ----
    {
        int warp = tid >> 5, lane = tid & 31;
#pragma unroll
        for (int cc = 0; cc < 4; cc++) {
            int c = warp * 4 + cc;
            const float* pv = vbase + (size_t)c * SPAT;
            float am0 = 0.f, am1 = 0.f, am2 = 0.f, am3 = 0.f;
            for (int q = 0; q < 32; q++) {
                int n = q * 32 + lane;
                float t2 = simval[n] * pv[q * 64 + lane];
                int m = mstar[n];
                am0 += (m == 0) ? t2 : 0.f;
                am1 += (m == 1) ? t2 : 0.f;
                am2 += (m == 2) ? t2 : 0.f;
                am3 += (m == 3) ? t2 : 0.f;
            }
            float am[4] = {am0, am1, am2, am3};
#pragma unroll
            for (int m = 0; m < 4; m++) {
                float s = am[m];
                for (int o = 16; o; o >>= 1) s += __shfl_down_sync(0xffffffffu, s, o);
                if (lane == 0) accs[m * 32 + c] = s;
            }
        }
        if (warp == 0) {
            float pc4[4] = {0.f, 0.f, 0.f, 0.f};
            for (int q = 0; q < 32; q++) pc4[mstar[q * 32 + lane]] += 1.f;
#pragma unroll
            for (int m = 0; m < 4; m++) {
                float s = pc4[m];
                for (int o = 16; o; o >>= 1) s += __shfl_down_sync(0xffffffffu, s, o);
                if (lane == 0) cnt[m] = s;
            }
        }
    }
    __syncthreads();
    if (tid < 128) outm[tid] = (accs[tid] + vcs[tid]) / (cnt[tid >> 5] + 1.f);
    __syncthreads();

    // ---- dispatch: token_out[n][c] = outm[m*][c] * sim[n]; write unfolded ----
    for (int idx = tid; idx < 32 * 1024; idx += 256) {
        int c = idx >> 10, n = idx & 1023;
        int wi = n >> 5, hj = n & 31;
        obase[(size_t)c * SPAT + wi * 64 + hj] = outm[mstar[n] * 32 + c] * simval[n];
    }
}

// ---------------- launcher ----------------
extern "C" void kernel_launch(void* const* d_in, const int* in_sizes, int n_in,
                              void* d_out, int out_size) {
    const float* x       = (const float*)d_in[0];
    const float* scaler  = (const float*)d_in[1];
    const float* w_fc1   = (const float*)d_in[2];
    const float* b_fc1   = (const float*)d_in[3];
    const float* w_fcv   = (const float*)d_in[4];
    const float* b_fcv   = (const float*)d_in[5];
    const float* w_fc2   = (const float*)d_in[6];
    const float* b_fc2   = (const float*)d_in[7];
    const float* alpha   = (const float*)d_in[8];
    const float* beta    = (const float*)d_in[9];
    const float* off_w1  = (const float*)d_in[10];
    const float* off_b1  = (const float*)d_in[11];
    const float* off_w2  = (const float*)d_in[12];
    const float* off_b2  = (const float*)d_in[13];
    float* out = (float*)d_out;

    int B = in_sizes[0] / (DIMC * SPAT);
    if (B > MAXB) B = MAXB;

    // device scratch pointers
    float *p_mean, *p_bb, *p_wcat, *p_xv, *p_x2;
    cudaGetSymbolAddress((void**)&p_mean, g_mean);
    cudaGetSymbolAddress((void**)&p_bb,   g_bb);
    cudaGetSymbolAddress((void**)&p_wcat, g_wcat);
    cudaGetSymbolAddress((void**)&p_xv,   g_xv);
    cudaGetSymbolAddress((void**)&p_x2,   g_x2);

    // 1. spatial means
    mean_kernel<<<B * DIMC, 256>>>(x, p_mean);
    // 2. weight concat + adjusted bias
    wcat_kernel<<<512, 256>>>(w_fc1, w_fcv);
    bias_kernel<<<(B * 512 + 255) / 256, 256>>>(w_fc1, b_fc1, w_fcv, b_fcv, scaler, B);
    // 3. fused fc1+fcv GEMM on raw x (gap correction folded into bias)
    {
        dim3 grid(SPAT / BN, 512 / BM, B);
        sgemm_kernel<<<grid, 256>>>(p_wcat, x, p_bb, p_xv, 512, DIMC, SPAT, 1);
    }
    // 4. clustering per fold window
    cluster_kernel<<<B * 32, 256>>>(off_w1, off_b1, off_w2, off_b2, alpha, beta);
    // 5. fc2 GEMM -> output
    {
        dim3 grid(SPAT / BN, DIMC / BM, B);
        sgemm_kernel<<<grid, 256>>>(w_fc2, p_x2, b_fc2, out, DIMC, DIMC, SPAT, 0);
    }
}

// round 5
// speedup vs baseline: 1.7621x; 1.7618x over previous
#include <cuda_runtime.h>
#include <cuda_bf16.h>
#include <cstdint>
#include <math.h>

// ---------------- problem constants ----------------
#define DIMC   256
#define SPAT   4096
#define NHEAD  8
#define HDIM   32
#define HIDM   53
#define MAXB   16

// ---------------- device scratch ----------------
__device__ float g_mean[MAXB * DIMC];
__device__ float g_bb[MAXB * 512];
__device__ __nv_bfloat16 g_w1hi[512 * DIMC], g_w1lo[512 * DIMC];      // [fc1;fcv] split
__device__ __nv_bfloat16 g_w2hi[DIMC * DIMC], g_w2lo[DIMC * DIMC];    // fc2 split
__device__ __nv_bfloat16 g_xthi[(size_t)MAXB * SPAT * DIMC];          // X^T [b][s][k]
__device__ __nv_bfloat16 g_xtlo[(size_t)MAXB * SPAT * DIMC];
__device__ __nv_bfloat16 g_gthi[(size_t)MAXB * SPAT * DIMC];          // cluster out^T
__device__ __nv_bfloat16 g_gtlo[(size_t)MAXB * SPAT * DIMC];
__device__ float g_xv[(size_t)MAXB * 512 * SPAT];                     // fc1+fcv out fp32

// ---------------- PTX helpers (sm_80-era only; no tcgen05 on this target) ----------------
__device__ __forceinline__ uint32_t smem_u32(const void* p) {
    uint32_t a;
    asm("{ .reg .u64 t; cvta.to.shared.u64 t, %1; cvt.u32.u64 %0, t; }" : "=r"(a) : "l"(p));
    return a;
}
__device__ __forceinline__ void cp_async16(uint32_t s, const void* g) {
    asm volatile("cp.async.cg.shared.global [%0], [%1], 16;" :: "r"(s), "l"(g));
}
#define CP_COMMIT() asm volatile("cp.async.commit_group;" ::: "memory")
#define CP_WAIT(n)  asm volatile("cp.async.wait_group %0;" :: "n"(n) : "memory")

__device__ __forceinline__ void ldsm4(uint32_t* r, uint32_t a) {
    asm volatile("ldmatrix.sync.aligned.m8n8.x4.shared.b16 {%0,%1,%2,%3}, [%4];"
        : "=r"(r[0]), "=r"(r[1]), "=r"(r[2]), "=r"(r[3]) : "r"(a));
}
__device__ __forceinline__ void mma_bf16(float* d, const uint32_t* a, const uint32_t* b) {
    asm volatile("mma.sync.aligned.m16n8k16.row.col.f32.bf16.bf16.f32 "
        "{%0,%1,%2,%3}, {%4,%5,%6,%7}, {%8,%9}, {%0,%1,%2,%3};"
        : "+f"(d[0]), "+f"(d[1]), "+f"(d[2]), "+f"(d[3])
        : "r"(a[0]), "r"(a[1]), "r"(a[2]), "r"(a[3]), "r"(b[0]), "r"(b[1]));
}

__device__ __forceinline__ void bsplit(float v, __nv_bfloat16& h, __nv_bfloat16& l) {
    h = __float2bfloat16(v);
    l = __float2bfloat16(v - __bfloat162float(h));
}

// smem tile: 128 rows x 32 bf16 (64B/row), 16B-chunk XOR swizzle -> conflict-free ldmatrix
__device__ __forceinline__ uint32_t sw_off(int row, int chunk) {
    return (uint32_t)(row * 64 + ((chunk ^ ((row >> 1) & 3)) << 4));
}

// ---------------- kernel 1: spatial mean ----------------
__global__ void mean_kernel(const float* __restrict__ x, float* __restrict__ meanOut) {
    int bc = blockIdx.x;
    const float* p = x + (size_t)bc * SPAT;
    float s = 0.f;
    for (int i = threadIdx.x; i < SPAT; i += 256) s += p[i];
    __shared__ float red[256];
    red[threadIdx.x] = s;
    __syncthreads();
    for (int off = 128; off > 0; off >>= 1) {
        if (threadIdx.x < off) red[threadIdx.x] += red[threadIdx.x + off];
        __syncthreads();
    }
    if (threadIdx.x == 0) meanOut[bc] = red[0] * (1.f / (float)SPAT);
}

// ---------------- kernel 2: adjusted bias ----------------
__global__ void bias_kernel(const float* __restrict__ w1, const float* __restrict__ b1,
                            const float* __restrict__ wv, const float* __restrict__ bv,
                            const float* __restrict__ scaler, int B) {
    int id = blockIdx.x * blockDim.x + threadIdx.x;
    if (id >= B * 512) return;
    int b = id >> 9, r = id & 511;
    const float* w = (r < 256) ? (w1 + (size_t)r * DIMC) : (wv + (size_t)(r - 256) * DIMC);
    float base = (r < 256) ? b1[r] : bv[r - 256];
    const float* mn = g_mean + b * DIMC;
    float s = 0.f;
#pragma unroll 8
    for (int c = 0; c < DIMC; c++) s += w[c] * scaler[c] * mn[c];
    g_bb[id] = base + s;
}

// ---------------- kernel 3: weight split ----------------
__global__ void convw_kernel(const float* __restrict__ w1, const float* __restrict__ wv,
                             const float* __restrict__ w2) {
    int i = blockIdx.x * blockDim.x + threadIdx.x;
    if (i < 65536) {
        bsplit(w1[i], g_w1hi[i], g_w1lo[i]);
    } else if (i < 131072) {
        bsplit(wv[i - 65536], g_w1hi[i], g_w1lo[i]);
    } else if (i < 196608) {
        bsplit(w2[i - 131072], g_w2hi[i - 131072], g_w2lo[i - 131072]);
    }
}

// ---------------- kernel 4: transpose+split x -> X^T hi/lo ----------------
__global__ void convx_kernel(const float* __restrict__ x) {
    __shared__ float t[32][33];
    int s0 = blockIdx.x * 32, c0 = blockIdx.y * 32, b = blockIdx.z;
    int tx = threadIdx.x, ty = threadIdx.y;
#pragma unroll
    for (int i = 0; i < 4; i++)
        t[ty + i * 8][tx] = x[((size_t)(b * DIMC + c0 + ty + i * 8)) * SPAT + s0 + tx];
    __syncthreads();
#pragma unroll
    for (int i = 0; i < 4; i++) {
        int s = s0 + ty + i * 8;
        float v = t[tx][ty + i * 8];
        __nv_bfloat16 h, l;
        bsplit(v, h, l);
        size_t o = ((size_t)b * SPAT + s) * DIMC + c0 + tx;
        g_xthi[o] = h;
        g_xtlo[o] = l;
    }
}

// ---------------- kernel 5/7: HMMA bf16-split GEMM ----------------
// O[b,m,n] = sum_k W[m,k]*X[b][n][k] + bias, 3-term bf16 split, fp32 accum.
// 128x128 block tile, BK=32, 8 warps x (64x32) warp tiles, cp.async double buffer.
__global__ __launch_bounds__(256)
void gemm_hmma_kernel(const __nv_bfloat16* __restrict__ whi, const __nv_bfloat16* __restrict__ wlo,
                      const __nv_bfloat16* __restrict__ xhi, const __nv_bfloat16* __restrict__ xlo,
                      const float* __restrict__ bias, float* __restrict__ O,
                      int M, int biasPerBatch) {
    extern __shared__ __align__(1024) char sm[];   // 2 stages x 4 tiles x 8KB = 64KB
    const int tid = threadIdx.x, lane = tid & 31, warp = tid >> 5;
    const int b = blockIdx.z, n0 = blockIdx.x * 128, m0 = blockIdx.y * 128;
    const int wm = (warp >> 2) * 64, wn = (warp & 3) * 32;

    const __nv_bfloat16* srcs[4] = {
        whi + (size_t)m0 * DIMC, wlo + (size_t)m0 * DIMC,
        xhi + ((size_t)b * SPAT + n0) * DIMC, xlo + ((size_t)b * SPAT + n0) * DIMC };
    const uint32_t smb = smem_u32(sm);

    float acc[4][4][4];
#pragma unroll
    for (int i = 0; i < 4; i++)
#pragma unroll
        for (int j = 0; j < 4; j++)
#pragma unroll
            for (int k = 0; k < 4; k++) acc[i][j][k] = 0.f;

    auto load_stage = [&](int stage, int kc) {
#pragma unroll
        for (int t = 0; t < 4; t++) {
#pragma unroll
            for (int i = 0; i < 2; i++) {
                int chunkid = tid + 256 * i;
                int row = chunkid >> 2, c = chunkid & 3;
                cp_async16(smb + stage * 32768 + t * 8192 + sw_off(row, c),
                           srcs[t] + (size_t)row * DIMC + kc * 32 + c * 8);
            }
        }
        CP_COMMIT();
    };

    const int rl = lane & 7, sel = lane >> 3;

    load_stage(0, 0);
    int stage = 0;
    for (int kc = 0; kc < 8; kc++) {
        if (kc + 1 < 8) { load_stage(stage ^ 1, kc + 1); CP_WAIT(1); }
        else            { CP_WAIT(0); }
        __syncthreads();

        const uint32_t base = smb + stage * 32768;
#pragma unroll
        for (int ks = 0; ks < 2; ks++) {
            uint32_t ahi[4][4], alo[4][4];
#pragma unroll
            for (int mt = 0; mt < 4; mt++) {
                int row = wm + mt * 16 + (sel & 1) * 8 + rl;
                int ch = ks * 2 + (sel >> 1);
                uint32_t o = sw_off(row, ch);
                ldsm4(ahi[mt], base + o);            // Ahi tile
                ldsm4(alo[mt], base + 8192 + o);     // Alo tile
            }
            uint32_t bhi[4][2], blo[4][2];
#pragma unroll
            for (int p = 0; p < 2; p++) {
                int row = wn + p * 16 + (sel >> 1) * 8 + rl;
                int ch = ks * 2 + (sel & 1);
                uint32_t o = sw_off(row, ch);
                uint32_t r4[4];
                ldsm4(r4, base + 16384 + o);         // Bhi tile
                bhi[2 * p][0] = r4[0]; bhi[2 * p][1] = r4[1];
                bhi[2 * p + 1][0] = r4[2]; bhi[2 * p + 1][1] = r4[3];
                ldsm4(r4, base + 24576 + o);         // Blo tile
                blo[2 * p][0] = r4[0]; blo[2 * p][1] = r4[1];
                blo[2 * p + 1][0] = r4[2]; blo[2 * p + 1][1] = r4[3];
            }
#pragma unroll
            for (int mt = 0; mt < 4; mt++)
#pragma unroll
                for (int nt = 0; nt < 4; nt++) {
                    mma_bf16(acc[mt][nt], ahi[mt], bhi[nt]);
                    mma_bf16(acc[mt][nt], ahi[mt], blo[nt]);
                    mma_bf16(acc[mt][nt], alo[mt], bhi[nt]);
                }
        }
        __syncthreads();
        stage ^= 1;
    }

    // epilogue: bias + direct float2 stores (each quad -> one 32B sector)
    const int g = lane >> 2, tig = lane & 3;
    const int bofs = biasPerBatch ? b * M : 0;
#pragma unroll
    for (int mt = 0; mt < 4; mt++) {
        int r0 = m0 + wm + mt * 16 + g;
        float b0v = bias[bofs + r0];
        float b1v = bias[bofs + r0 + 8];
        float* orow0 = O + ((size_t)b * M + r0) * SPAT + n0;
        float* orow1 = orow0 + (size_t)8 * SPAT;
#pragma unroll
        for (int nt = 0; nt < 4; nt++) {
            int col = wn + nt * 8 + 2 * tig;
            float2 v0 = make_float2(acc[mt][nt][0] + b0v, acc[mt][nt][1] + b0v);
            float2 v1 = make_float2(acc[mt][nt][2] + b1v, acc[mt][nt][3] + b1v);
            *reinterpret_cast<float2*>(orow0 + col) = v0;
            *reinterpret_cast<float2*>(orow1 + col) = v1;
        }
    }
}

// ---------------- kernel 6: clustering ----------------
__global__ __launch_bounds__(256)
void cluster_kernel(const float* __restrict__ w1, const float* __restrict__ bb1,
                    const float* __restrict__ w2, const float* __restrict__ bb2,
                    const float* __restrict__ alphaP, const float* __restrict__ betaP) {
    const int tid = threadIdx.x;
    const int bbk = blockIdx.x;
    const int bh = bbk >> 2;
    const int fi = (bbk >> 1) & 1;
    const int fj = bbk & 1;
    const int batch = bh >> 3;
    const int head = bh & 7;

    const size_t foldoff = (size_t)fi * 32 * 64 + (size_t)fj * 32;
    const float* xbase = g_xv + ((size_t)batch * 512 + head * HDIM) * SPAT + foldoff;
    const float* vbase = xbase + (size_t)256 * SPAT;

    __shared__ float a8[2048];
    __shared__ float hbuf[HIDM * 64];
    __shared__ float w1s[HIDM * HDIM], b1s[HIDM], w2s[HDIM * HIDM], b2s[HDIM];
    __shared__ float ctrs[128], vcs[128], cns[128], outm[128], accs[128], cavg[128];
    __shared__ float cnorm[4], cnt[4];
    __shared__ float simval[1024];
    __shared__ unsigned char mstar[1024];

    for (int i = tid; i < HIDM * HDIM; i += 256) { w1s[i] = w1[i]; w2s[i] = w2[i]; }
    if (tid < HIDM) b1s[tid] = bb1[tid];
    if (tid < HDIM) b2s[tid] = bb2[tid];

    for (int pass = 0; pass < 2; pass++) {
        const float* src = (pass == 0) ? vbase : xbase;
        float* dst = (pass == 0) ? vcs : ctrs;
        __syncthreads();
#pragma unroll
        for (int rep = 0; rep < 8; rep++) {
            int e = rep * 256 + tid;
            int c = e >> 6, pos = e & 63, pi = pos >> 3, pj = pos & 7;
            const float* pc = src + (size_t)c * SPAT;
            float s = 0.f;
#pragma unroll
            for (int u = 0; u < 4; u++)
#pragma unroll
                for (int v2 = 0; v2 < 4; v2++)
                    s += pc[(pi * 4 + u) * 64 + pj * 4 + v2];
            a8[c * 64 + pos] = s * (1.f / 16.f);
        }
        __syncthreads();
        if (tid < 128) {
            int m = tid >> 5, c = tid & 31, qi = m >> 1, qj = m & 1;
            float s = 0.f;
#pragma unroll
            for (int u = 0; u < 4; u++)
#pragma unroll
                for (int v2 = 0; v2 < 4; v2++)
                    s += a8[c * 64 + (qi * 4 + u) * 8 + qj * 4 + v2];
            cavg[tid] = s * (1.f / 16.f);
        }
        for (int eh = tid; eh < HIDM * 64; eh += 256) {
            int j = eh >> 6, p = eh & 63;
            float s = b1s[j];
#pragma unroll
            for (int c = 0; c < HDIM; c++) s += w1s[j * HDIM + c] * a8[c * 64 + p];
            hbuf[eh] = 0.5f * s * (1.f + erff(s * 0.70710678118654752440f));
        }
        __syncthreads();
        for (int eo = tid; eo < 2048; eo += 256) {
            int c = eo >> 6, p = eo & 63;
            float s = b2s[c];
#pragma unroll
            for (int j = 0; j < HIDM; j++) s += w2s[c * HIDM + j] * hbuf[j * 64 + p];
            a8[eo] = s;
        }
        __syncthreads();
        if (tid < 128) {
            int m = tid >> 5, c = tid & 31, qi = m >> 1, qj = m & 1;
            float mx = -INFINITY;
#pragma unroll
            for (int u = 0; u < 4; u++)
#pragma unroll
                for (int v2 = 0; v2 < 4; v2++)
                    mx = fmaxf(mx, a8[c * 64 + (qi * 4 + u) * 8 + qj * 4 + v2]);
            dst[tid] = cavg[tid] + mx;
        }
        __syncthreads();
    }

    if (tid < 4) {
        float s = 0.f;
#pragma unroll
        for (int c = 0; c < HDIM; c++) { float v = ctrs[tid * 32 + c]; s += v * v; }
        cnorm[tid] = fmaxf(sqrtf(s), 1e-12f);
    }
    __syncthreads();
    if (tid < 128) cns[tid] = ctrs[tid] / cnorm[tid >> 5];
    __syncthreads();

    const float alpha = alphaP[0], beta = betaP[0];

#pragma unroll
    for (int rep = 0; rep < 4; rep++) {
        int n = rep * 256 + tid;
        int wi = n >> 5, hj = n & 31;
        const float* px = xbase + wi * 64 + hj;
        float xt[32];
        float ss = 0.f;
#pragma unroll
        for (int c = 0; c < HDIM; c++) { float v = px[c * SPAT]; xt[c] = v; ss += v * v; }
        float inv = 1.f / fmaxf(sqrtf(ss), 1e-12f);
        float best = -1.f; int bm = 0;
#pragma unroll
        for (int m = 0; m < 4; m++) {
            float d = 0.f;
#pragma unroll
            for (int c = 0; c < HDIM; c++) d += cns[m * 32 + c] * xt[c];
            d *= inv;
            float sg = 1.f / (1.f + expf(-(beta + alpha * d)));
            if (sg > best) { best = sg; bm = m; }
        }
        simval[n] = best;
        mstar[n] = (unsigned char)bm;
    }
    __syncthreads();

    {
        int warp = tid >> 5, lane = tid & 31;
#pragma unroll
        for (int cc = 0; cc < 4; cc++) {
            int c = warp * 4 + cc;
            const float* pv = vbase + (size_t)c * SPAT;
            float am0 = 0.f, am1 = 0.f, am2 = 0.f, am3 = 0.f;
            for (int q = 0; q < 32; q++) {
                int n = q * 32 + lane;
                float t2 = simval[n] * pv[q * 64 + lane];
                int m = mstar[n];
                am0 += (m == 0) ? t2 : 0.f;
                am1 += (m == 1) ? t2 : 0.f;
                am2 += (m == 2) ? t2 : 0.f;
                am3 += (m == 3) ? t2 : 0.f;
            }
            float am[4] = {am0, am1, am2, am3};
#pragma unroll
            for (int m = 0; m < 4; m++) {
                float s = am[m];
                for (int o = 16; o; o >>= 1) s += __shfl_down_sync(0xffffffffu, s, o);
                if (lane == 0) accs[m * 32 + c] = s;
            }
        }
        if (warp == 0) {
            float pc4[4] = {0.f, 0.f, 0.f, 0.f};
            for (int q = 0; q < 32; q++) pc4[mstar[q * 32 + lane]] += 1.f;
#pragma unroll
            for (int m = 0; m < 4; m++) {
                float s = pc4[m];
                for (int o = 16; o; o >>= 1) s += __shfl_down_sync(0xffffffffu, s, o);
                if (lane == 0) cnt[m] = s;
            }
        }
    }
    __syncthreads();
    if (tid < 128) outm[tid] = (accs[tid] + vcs[tid]) / (cnt[tid >> 5] + 1.f);
    __syncthreads();

    // dispatch: write directly transposed + bf16-split for the fc2 GEMM
    for (int n = tid; n < 1024; n += 256) {
        int wi = n >> 5, hj = n & 31;
        int s = (fi * 32 + wi) * 64 + (fj * 32 + hj);
        float sv = simval[n];
        int m = mstar[n];
        size_t o = ((size_t)batch * SPAT + s) * DIMC + head * HDIM;
        __nv_bfloat162* ph = (__nv_bfloat162*)(g_gthi + o);
        __nv_bfloat162* pl = (__nv_bfloat162*)(g_gtlo + o);
#pragma unroll
        for (int cc = 0; cc < 16; cc++) {
            float v0 = outm[m * 32 + cc * 2] * sv;
            float v1 = outm[m * 32 + cc * 2 + 1] * sv;
            __nv_bfloat16 h0, l0, h1, l1;
            bsplit(v0, h0, l0);
            bsplit(v1, h1, l1);
            ph[cc] = __halves2bfloat162(h0, h1);
            pl[cc] = __halves2bfloat162(l0, l1);
        }
    }
}

// ---------------- launcher ----------------
extern "C" void kernel_launch(void* const* d_in, const int* in_sizes, int n_in,
                              void* d_out, int out_size) {
    const float* x      = (const float*)d_in[0];
    const float* scaler = (const float*)d_in[1];
    const float* w_fc1  = (const float*)d_in[2];
    const float* b_fc1  = (const float*)d_in[3];
    const float* w_fcv  = (const float*)d_in[4];
    const float* b_fcv  = (const float*)d_in[5];
    const float* w_fc2  = (const float*)d_in[6];
    const float* b_fc2  = (const float*)d_in[7];
    const float* alpha  = (const float*)d_in[8];
    const float* beta   = (const float*)d_in[9];
    const float* off_w1 = (const float*)d_in[10];
    const float* off_b1 = (const float*)d_in[11];
    const float* off_w2 = (const float*)d_in[12];
    const float* off_b2 = (const float*)d_in[13];
    float* out = (float*)d_out;

    int B = in_sizes[0] / (DIMC * SPAT);
    if (B > MAXB) B = MAXB;

    float *p_mean, *p_bb, *p_xv;
    __nv_bfloat16 *p_w1h, *p_w1l, *p_w2h, *p_w2l, *p_xth, *p_xtl, *p_gth, *p_gtl;
    cudaGetSymbolAddress((void**)&p_mean, g_mean);
    cudaGetSymbolAddress((void**)&p_bb,   g_bb);
    cudaGetSymbolAddress((void**)&p_xv,   g_xv);
    cudaGetSymbolAddress((void**)&p_w1h,  g_w1hi);
    cudaGetSymbolAddress((void**)&p_w1l,  g_w1lo);
    cudaGetSymbolAddress((void**)&p_w2h,  g_w2hi);
    cudaGetSymbolAddress((void**)&p_w2l,  g_w2lo);
    cudaGetSymbolAddress((void**)&p_xth,  g_xthi);
    cudaGetSymbolAddress((void**)&p_xtl,  g_xtlo);
    cudaGetSymbolAddress((void**)&p_gth,  g_gthi);
    cudaGetSymbolAddress((void**)&p_gtl,  g_gtlo);

    static bool attr_set = false;
    if (!attr_set) {
        cudaFuncSetAttribute(gemm_hmma_kernel, cudaFuncAttributeMaxDynamicSharedMemorySize, 65536);
        attr_set = true;
    }

    // 1. spatial means + adjusted bias
    mean_kernel<<<B * DIMC, 256>>>(x, p_mean);
    bias_kernel<<<(B * 512 + 255) / 256, 256>>>(w_fc1, b_fc1, w_fcv, b_fcv, scaler, B);
    // 2. weight splits, input transpose+split
    convw_kernel<<<768, 256>>>(w_fc1, w_fcv, w_fc2);
    {
        dim3 g(SPAT / 32, DIMC / 32, B);
        convx_kernel<<<g, dim3(32, 8)>>>(x);
    }
    // 3. fused fc1+fcv tensor-core GEMM (gap correction folded into bias)
    {
        dim3 grid(SPAT / 128, 512 / 128, B);
        gemm_hmma_kernel<<<grid, 256, 65536>>>(p_w1h, p_w1l, p_xth, p_xtl, p_bb, p_xv, 512, 1);
    }
    // 4. clustering; writes transposed bf16-split output for fc2
    cluster_kernel<<<B * 32, 256>>>(off_w1, off_b1, off_w2, off_b2, alpha, beta);
    // 5. fc2 tensor-core GEMM -> output
    {
        dim3 grid(SPAT / 128, DIMC / 128, B);
        gemm_hmma_kernel<<<grid, 256, 65536>>>(p_w2h, p_w2l, p_gth, p_gtl, b_fc2, out, DIMC, 0);
    }
}

// round 6
// speedup vs baseline: 2.2705x; 1.2885x over previous
#include <cuda_runtime.h>
#include <cuda_bf16.h>
#include <cstdint>
#include <math.h>

// ---------------- problem constants ----------------
#define DIMC   256
#define SPAT   4096
#define NHEAD  8
#define HDIM   32
#define HIDM   53
#define MAXB   16

// ---------------- device scratch ----------------
__device__ float g_mean[MAXB * DIMC];
__device__ float g_bb[MAXB * 512];
__device__ __nv_bfloat16 g_w1hi[512 * DIMC], g_w1lo[512 * DIMC];      // [fc1;fcv] split
__device__ __nv_bfloat16 g_xthi[(size_t)MAXB * SPAT * DIMC];          // X^T [b][s][k]
__device__ __nv_bfloat16 g_xtlo[(size_t)MAXB * SPAT * DIMC];
__device__ float g_xv[(size_t)MAXB * 512 * SPAT];                     // fc1+fcv out fp32
__device__ float g_sim[(size_t)MAXB * 32 * 1024];                     // per-window token sim
__device__ unsigned char g_mstar[(size_t)MAXB * 32 * 1024];           // per-window argmax
__device__ float g_y[(size_t)MAXB * 32 * 4 * 256];                    // W2 . outm per cluster

// ---------------- PTX helpers (sm_80-era only; no tcgen05 on this target) ----------------
__device__ __forceinline__ uint32_t smem_u32(const void* p) {
    uint32_t a;
    asm("{ .reg .u64 t; cvta.to.shared.u64 t, %1; cvt.u32.u64 %0, t; }" : "=r"(a) : "l"(p));
    return a;
}
__device__ __forceinline__ void cp_async16(uint32_t s, const void* g) {
    asm volatile("cp.async.cg.shared.global [%0], [%1], 16;" :: "r"(s), "l"(g));
}
#define CP_COMMIT() asm volatile("cp.async.commit_group;" ::: "memory")
#define CP_WAIT(n)  asm volatile("cp.async.wait_group %0;" :: "n"(n) : "memory")

__device__ __forceinline__ void ldsm4(uint32_t* r, uint32_t a) {
    asm volatile("ldmatrix.sync.aligned.m8n8.x4.shared.b16 {%0,%1,%2,%3}, [%4];"
        : "=r"(r[0]), "=r"(r[1]), "=r"(r[2]), "=r"(r[3]) : "r"(a));
}
__device__ __forceinline__ void mma_bf16(float* d, const uint32_t* a, const uint32_t* b) {
    asm volatile("mma.sync.aligned.m16n8k16.row.col.f32.bf16.bf16.f32 "
        "{%0,%1,%2,%3}, {%4,%5,%6,%7}, {%8,%9}, {%0,%1,%2,%3};"
        : "+f"(d[0]), "+f"(d[1]), "+f"(d[2]), "+f"(d[3])
        : "r"(a[0]), "r"(a[1]), "r"(a[2]), "r"(a[3]), "r"(b[0]), "r"(b[1]));
}

__device__ __forceinline__ void bsplit(float v, __nv_bfloat16& h, __nv_bfloat16& l) {
    h = __float2bfloat16(v);
    l = __float2bfloat16(v - __bfloat162float(h));
}

// smem tile: 128 rows x 32 bf16 (64B/row), 16B-chunk XOR swizzle -> conflict-free ldmatrix
__device__ __forceinline__ uint32_t sw_off(int row, int chunk) {
    return (uint32_t)(row * 64 + ((chunk ^ ((row >> 1) & 3)) << 4));
}

// ---------------- kernel 1: spatial mean ----------------
__global__ void mean_kernel(const float* __restrict__ x, float* __restrict__ meanOut) {
    int bc = blockIdx.x;
    const float* p = x + (size_t)bc * SPAT;
    float s = 0.f;
    for (int i = threadIdx.x; i < SPAT; i += 256) s += p[i];
    __shared__ float red[256];
    red[threadIdx.x] = s;
    __syncthreads();
    for (int off = 128; off > 0; off >>= 1) {
        if (threadIdx.x < off) red[threadIdx.x] += red[threadIdx.x + off];
        __syncthreads();
    }
    if (threadIdx.x == 0) meanOut[bc] = red[0] * (1.f / (float)SPAT);
}

// ---------------- kernel 2: adjusted bias ----------------
__global__ void bias_kernel(const float* __restrict__ w1, const float* __restrict__ b1,
                            const float* __restrict__ wv, const float* __restrict__ bv,
                            const float* __restrict__ scaler, int B) {
    int id = blockIdx.x * blockDim.x + threadIdx.x;
    if (id >= B * 512) return;
    int b = id >> 9, r = id & 511;
    const float* w = (r < 256) ? (w1 + (size_t)r * DIMC) : (wv + (size_t)(r - 256) * DIMC);
    float base = (r < 256) ? b1[r] : bv[r - 256];
    const float* mn = g_mean + b * DIMC;
    float s = 0.f;
#pragma unroll 8
    for (int c = 0; c < DIMC; c++) s += w[c] * scaler[c] * mn[c];
    g_bb[id] = base + s;
}

// ---------------- kernel 3: weight split (fc1/fcv only; fc2 stays exact fp32) ----------------
__global__ void convw_kernel(const float* __restrict__ w1, const float* __restrict__ wv) {
    int i = blockIdx.x * blockDim.x + threadIdx.x;
    if (i < 65536) {
        bsplit(w1[i], g_w1hi[i], g_w1lo[i]);
    } else if (i < 131072) {
        bsplit(wv[i - 65536], g_w1hi[i], g_w1lo[i]);
    }
}

// ---------------- kernel 4: transpose+split x -> X^T hi/lo ----------------
__global__ void convx_kernel(const float* __restrict__ x) {
    __shared__ float t[32][33];
    int s0 = blockIdx.x * 32, c0 = blockIdx.y * 32, b = blockIdx.z;
    int tx = threadIdx.x, ty = threadIdx.y;
#pragma unroll
    for (int i = 0; i < 4; i++)
        t[ty + i * 8][tx] = x[((size_t)(b * DIMC + c0 + ty + i * 8)) * SPAT + s0 + tx];
    __syncthreads();
#pragma unroll
    for (int i = 0; i < 4; i++) {
        int s = s0 + ty + i * 8;
        float v = t[tx][ty + i * 8];
        __nv_bfloat16 h, l;
        bsplit(v, h, l);
        size_t o = ((size_t)b * SPAT + s) * DIMC + c0 + tx;
        g_xthi[o] = h;
        g_xtlo[o] = l;
    }
}

// ---------------- kernel 5: HMMA bf16-split GEMM (fc1+fcv fused) ----------------
__global__ __launch_bounds__(256)
void gemm_hmma_kernel(const __nv_bfloat16* __restrict__ whi, const __nv_bfloat16* __restrict__ wlo,
                      const __nv_bfloat16* __restrict__ xhi, const __nv_bfloat16* __restrict__ xlo,
                      const float* __restrict__ bias, float* __restrict__ O,
                      int M, int biasPerBatch) {
    extern __shared__ __align__(1024) char sm[];   // 2 stages x 4 tiles x 8KB = 64KB
    const int tid = threadIdx.x, lane = tid & 31, warp = tid >> 5;
    const int b = blockIdx.z, n0 = blockIdx.x * 128, m0 = blockIdx.y * 128;
    const int wm = (warp >> 2) * 64, wn = (warp & 3) * 32;

    const __nv_bfloat16* srcs[4] = {
        whi + (size_t)m0 * DIMC, wlo + (size_t)m0 * DIMC,
        xhi + ((size_t)b * SPAT + n0) * DIMC, xlo + ((size_t)b * SPAT + n0) * DIMC };
    const uint32_t smb = smem_u32(sm);

    float acc[4][4][4];
#pragma unroll
    for (int i = 0; i < 4; i++)
#pragma unroll
        for (int j = 0; j < 4; j++)
#pragma unroll
            for (int k = 0; k < 4; k++) acc[i][j][k] = 0.f;

    auto load_stage = [&](int stage, int kc) {
#pragma unroll
        for (int t = 0; t < 4; t++) {
#pragma unroll
            for (int i = 0; i < 2; i++) {
                int chunkid = tid + 256 * i;
                int row = chunkid >> 2, c = chunkid & 3;
                cp_async16(smb + stage * 32768 + t * 8192 + sw_off(row, c),
                           srcs[t] + (size_t)row * DIMC + kc * 32 + c * 8);
            }
        }
        CP_COMMIT();
    };

    const int rl = lane & 7, sel = lane >> 3;

    load_stage(0, 0);
    int stage = 0;
    for (int kc = 0; kc < 8; kc++) {
        if (kc + 1 < 8) { load_stage(stage ^ 1, kc + 1); CP_WAIT(1); }
        else            { CP_WAIT(0); }
        __syncthreads();

        const uint32_t base = smb + stage * 32768;
#pragma unroll
        for (int ks = 0; ks < 2; ks++) {
            uint32_t ahi[4][4], alo[4][4];
#pragma unroll
            for (int mt = 0; mt < 4; mt++) {
                int row = wm + mt * 16 + (sel & 1) * 8 + rl;
                int ch = ks * 2 + (sel >> 1);
                uint32_t o = sw_off(row, ch);
                ldsm4(ahi[mt], base + o);            // Ahi tile
                ldsm4(alo[mt], base + 8192 + o);     // Alo tile
            }
            uint32_t bhi[4][2], blo[4][2];
#pragma unroll
            for (int p = 0; p < 2; p++) {
                int row = wn + p * 16 + (sel >> 1) * 8 + rl;
                int ch = ks * 2 + (sel & 1);
                uint32_t o = sw_off(row, ch);
                uint32_t r4[4];
                ldsm4(r4, base + 16384 + o);         // Bhi tile
                bhi[2 * p][0] = r4[0]; bhi[2 * p][1] = r4[1];
                bhi[2 * p + 1][0] = r4[2]; bhi[2 * p + 1][1] = r4[3];
                ldsm4(r4, base + 24576 + o);         // Blo tile
                blo[2 * p][0] = r4[0]; blo[2 * p][1] = r4[1];
                blo[2 * p + 1][0] = r4[2]; blo[2 * p + 1][1] = r4[3];
            }
#pragma unroll
            for (int mt = 0; mt < 4; mt++)
#pragma unroll
                for (int nt = 0; nt < 4; nt++) {
                    mma_bf16(acc[mt][nt], ahi[mt], bhi[nt]);
                    mma_bf16(acc[mt][nt], ahi[mt], blo[nt]);
                    mma_bf16(acc[mt][nt], alo[mt], bhi[nt]);
                }
        }
        __syncthreads();
        stage ^= 1;
    }

    const int g = lane >> 2, tig = lane & 3;
    const int bofs = biasPerBatch ? b * M : 0;
#pragma unroll
    for (int mt = 0; mt < 4; mt++) {
        int r0 = m0 + wm + mt * 16 + g;
        float b0v = bias[bofs + r0];
        float b1v = bias[bofs + r0 + 8];
        float* orow0 = O + ((size_t)b * M + r0) * SPAT + n0;
        float* orow1 = orow0 + (size_t)8 * SPAT;
#pragma unroll
        for (int nt = 0; nt < 4; nt++) {
            int col = wn + nt * 8 + 2 * tig;
            float2 v0 = make_float2(acc[mt][nt][0] + b0v, acc[mt][nt][1] + b0v);
            float2 v1 = make_float2(acc[mt][nt][2] + b1v, acc[mt][nt][3] + b1v);
            *reinterpret_cast<float2*>(orow0 + col) = v0;
            *reinterpret_cast<float2*>(orow1 + col) = v1;
        }
    }
}

// ---------------- kernel 6: clustering (emits sim/mstar/y instead of dense dispatch) ----------------
__global__ __launch_bounds__(256)
void cluster_kernel(const float* __restrict__ w1, const float* __restrict__ bb1,
                    const float* __restrict__ w2, const float* __restrict__ bb2,
                    const float* __restrict__ alphaP, const float* __restrict__ betaP,
                    const float* __restrict__ w_fc2) {
    const int tid = threadIdx.x;
    const int bbk = blockIdx.x;
    const int bh = bbk >> 2;
    const int fi = (bbk >> 1) & 1;
    const int fj = bbk & 1;
    const int batch = bh >> 3;
    const int head = bh & 7;

    const size_t foldoff = (size_t)fi * 32 * 64 + (size_t)fj * 32;
    const float* xbase = g_xv + ((size_t)batch * 512 + head * HDIM) * SPAT + foldoff;
    const float* vbase = xbase + (size_t)256 * SPAT;

    __shared__ float a8[2048];
    __shared__ float hbuf[HIDM * 64];
    __shared__ float w1s[HIDM * HDIM], b1s[HIDM], w2s[HDIM * HIDM], b2s[HDIM];
    __shared__ float ctrs[128], vcs[128], cns[128], outm[128], accs[128], cavg[128];
    __shared__ float cnorm[4], cnt[4];
    __shared__ float simval[1024];
    __shared__ unsigned char mstar[1024];

    for (int i = tid; i < HIDM * HDIM; i += 256) { w1s[i] = w1[i]; w2s[i] = w2[i]; }
    if (tid < HIDM) b1s[tid] = bb1[tid];
    if (tid < HDIM) b2s[tid] = bb2[tid];

    for (int pass = 0; pass < 2; pass++) {
        const float* src = (pass == 0) ? vbase : xbase;
        float* dst = (pass == 0) ? vcs : ctrs;
        __syncthreads();
#pragma unroll
        for (int rep = 0; rep < 8; rep++) {
            int e = rep * 256 + tid;
            int c = e >> 6, pos = e & 63, pi = pos >> 3, pj = pos & 7;
            const float* pc = src + (size_t)c * SPAT;
            float s = 0.f;
#pragma unroll
            for (int u = 0; u < 4; u++)
#pragma unroll
                for (int v2 = 0; v2 < 4; v2++)
                    s += pc[(pi * 4 + u) * 64 + pj * 4 + v2];
            a8[c * 64 + pos] = s * (1.f / 16.f);
        }
        __syncthreads();
        if (tid < 128) {
            int m = tid >> 5, c = tid & 31, qi = m >> 1, qj = m & 1;
            float s = 0.f;
#pragma unroll
            for (int u = 0; u < 4; u++)
#pragma unroll
                for (int v2 = 0; v2 < 4; v2++)
                    s += a8[c * 64 + (qi * 4 + u) * 8 + qj * 4 + v2];
            cavg[tid] = s * (1.f / 16.f);
        }
        for (int eh = tid; eh < HIDM * 64; eh += 256) {
            int j = eh >> 6, p = eh & 63;
            float s = b1s[j];
#pragma unroll
            for (int c = 0; c < HDIM; c++) s += w1s[j * HDIM + c] * a8[c * 64 + p];
            hbuf[eh] = 0.5f * s * (1.f + erff(s * 0.70710678118654752440f));
        }
        __syncthreads();
        for (int eo = tid; eo < 2048; eo += 256) {
            int c = eo >> 6, p = eo & 63;
            float s = b2s[c];
#pragma unroll
            for (int j = 0; j < HIDM; j++) s += w2s[c * HIDM + j] * hbuf[j * 64 + p];
            a8[eo] = s;
        }
        __syncthreads();
        if (tid < 128) {
            int m = tid >> 5, c = tid & 31, qi = m >> 1, qj = m & 1;
            float mx = -INFINITY;
#pragma unroll
            for (int u = 0; u < 4; u++)
#pragma unroll
                for (int v2 = 0; v2 < 4; v2++)
                    mx = fmaxf(mx, a8[c * 64 + (qi * 4 + u) * 8 + qj * 4 + v2]);
            dst[tid] = cavg[tid] + mx;
        }
        __syncthreads();
    }

    if (tid < 4) {
        float s = 0.f;
#pragma unroll
        for (int c = 0; c < HDIM; c++) { float v = ctrs[tid * 32 + c]; s += v * v; }
        cnorm[tid] = fmaxf(sqrtf(s), 1e-12f);
    }
    __syncthreads();
    if (tid < 128) cns[tid] = ctrs[tid] / cnorm[tid >> 5];
    __syncthreads();

    const float alpha = alphaP[0], beta = betaP[0];

#pragma unroll
    for (int rep = 0; rep < 4; rep++) {
        int n = rep * 256 + tid;
        int wi = n >> 5, hj = n & 31;
        const float* px = xbase + wi * 64 + hj;
        float xt[32];
        float ss = 0.f;
#pragma unroll
        for (int c = 0; c < HDIM; c++) { float v = px[c * SPAT]; xt[c] = v; ss += v * v; }
        float inv = 1.f / fmaxf(sqrtf(ss), 1e-12f);
        float best = -1.f; int bm = 0;
#pragma unroll
        for (int m = 0; m < 4; m++) {
            float d = 0.f;
#pragma unroll
            for (int c = 0; c < HDIM; c++) d += cns[m * 32 + c] * xt[c];
            d *= inv;
            float sg = 1.f / (1.f + expf(-(beta + alpha * d)));
            if (sg > best) { best = sg; bm = m; }
        }
        simval[n] = best;
        mstar[n] = (unsigned char)bm;
    }
    __syncthreads();

    {
        int warp = tid >> 5, lane = tid & 31;
#pragma unroll
        for (int cc = 0; cc < 4; cc++) {
            int c = warp * 4 + cc;
            const float* pv = vbase + (size_t)c * SPAT;
            float am0 = 0.f, am1 = 0.f, am2 = 0.f, am3 = 0.f;
            for (int q = 0; q < 32; q++) {
                int n = q * 32 + lane;
                float t2 = simval[n] * pv[q * 64 + lane];
                int m = mstar[n];
                am0 += (m == 0) ? t2 : 0.f;
                am1 += (m == 1) ? t2 : 0.f;
                am2 += (m == 2) ? t2 : 0.f;
                am3 += (m == 3) ? t2 : 0.f;
            }
            float am[4] = {am0, am1, am2, am3};
#pragma unroll
            for (int m = 0; m < 4; m++) {
                float s = am[m];
                for (int o = 16; o; o >>= 1) s += __shfl_down_sync(0xffffffffu, s, o);
                if (lane == 0) accs[m * 32 + c] = s;
            }
        }
        if (warp == 0) {
            float pc4[4] = {0.f, 0.f, 0.f, 0.f};
            for (int q = 0; q < 32; q++) pc4[mstar[q * 32 + lane]] += 1.f;
#pragma unroll
            for (int m = 0; m < 4; m++) {
                float s = pc4[m];
                for (int o = 16; o; o >>= 1) s += __shfl_down_sync(0xffffffffu, s, o);
                if (lane == 0) cnt[m] = s;
            }
        }
    }
    __syncthreads();
    if (tid < 128) outm[tid] = (accs[tid] + vcs[tid]) / (cnt[tid >> 5] + 1.f);
    __syncthreads();

    // export sim/mstar
    for (int n = tid; n < 1024; n += 256) {
        size_t sb = (size_t)bbk * 1024 + n;
        g_sim[sb] = simval[n];
        g_mstar[sb] = mstar[n];
    }
    // y[m][o] = sum_c w_fc2[o][head*32+c] * outm[m*32+c]  (exact fp32; replaces GEMM2)
    {
        const int o = tid;
        const float* w2row = w_fc2 + (size_t)o * DIMC + head * HDIM;
        float w2r[32];
#pragma unroll
        for (int c = 0; c < HDIM; c++) w2r[c] = w2row[c];
#pragma unroll
        for (int m = 0; m < 4; m++) {
            float s = 0.f;
#pragma unroll
            for (int c = 0; c < HDIM; c++) s += w2r[c] * outm[m * 32 + c];
            g_y[(size_t)bbk * 1024 + m * 256 + o] = s;
        }
    }
}

// ---------------- kernel 7: combine -> final output (replaces fc2 GEMM) ----------------
// out[b][o][s] = b2[o] + sum_h sim_h(s) * y[b,h,win(s)][mstar_h(s)][o]
__global__ __launch_bounds__(256)
void combine_kernel(const float* __restrict__ b2, float* __restrict__ out) {
    const int o0 = blockIdx.x * 32;        // 8 o-chunks
    const int win = blockIdx.y;            // 0..3
    const int batch = blockIdx.z;
    const int fi = win >> 1, fj = win & 1;
    const int tid = threadIdx.x, lane = tid & 31, warp = tid >> 5;

    __shared__ float ys[8][4][33];         // padded: m-gather conflict-free
    __shared__ float b2s[32];

    for (int i = tid; i < 8 * 4 * 32; i += 256) {
        int h = i >> 7, m = (i >> 5) & 3, o = i & 31;
        ys[h][m][o] = g_y[((size_t)(batch * 8 + h) * 4 + win) * 1024 + m * 256 + o0 + o];
    }
    if (tid < 32) b2s[tid] = b2[o0 + tid];
    __syncthreads();

#pragma unroll
    for (int r = 0; r < 4; r++) {
        int wi = warp * 4 + r;
        int n = wi * 32 + lane;
        float simr[8];
        int mr[8];
#pragma unroll
        for (int h = 0; h < 8; h++) {
            size_t sb = ((size_t)(batch * 8 + h) * 4 + win) * 1024 + n;
            simr[h] = g_sim[sb];
            mr[h] = g_mstar[sb];
        }
        int s = (fi * 32 + wi) * 64 + fj * 32 + lane;
        float* op = out + ((size_t)batch * DIMC + o0) * SPAT + s;
#pragma unroll
        for (int o = 0; o < 32; o++) {
            float acc = b2s[o];
#pragma unroll
            for (int h = 0; h < 8; h++) acc += simr[h] * ys[h][mr[h]][o];
            op[(size_t)o * SPAT] = acc;
        }
    }
}

// ---------------- launcher ----------------
extern "C" void kernel_launch(void* const* d_in, const int* in_sizes, int n_in,
                              void* d_out, int out_size) {
    const float* x      = (const float*)d_in[0];
    const float* scaler = (const float*)d_in[1];
    const float* w_fc1  = (const float*)d_in[2];
    const float* b_fc1  = (const float*)d_in[3];
    const float* w_fcv  = (const float*)d_in[4];
    const float* b_fcv  = (const float*)d_in[5];
    const float* w_fc2  = (const float*)d_in[6];
    const float* b_fc2  = (const float*)d_in[7];
    const float* alpha  = (const float*)d_in[8];
    const float* beta   = (const float*)d_in[9];
    const float* off_w1 = (const float*)d_in[10];
    const float* off_b1 = (const float*)d_in[11];
    const float* off_w2 = (const float*)d_in[12];
    const float* off_b2 = (const float*)d_in[13];
    float* out = (float*)d_out;

    int B = in_sizes[0] / (DIMC * SPAT);
    if (B > MAXB) B = MAXB;

    float *p_mean, *p_bb, *p_xv;
    __nv_bfloat16 *p_w1h, *p_w1l, *p_xth, *p_xtl;
    cudaGetSymbolAddress((void**)&p_mean, g_mean);
    cudaGetSymbolAddress((void**)&p_bb,   g_bb);
    cudaGetSymbolAddress((void**)&p_xv,   g_xv);
    cudaGetSymbolAddress((void**)&p_w1h,  g_w1hi);
    cudaGetSymbolAddress((void**)&p_w1l,  g_w1lo);
    cudaGetSymbolAddress((void**)&p_xth,  g_xthi);
    cudaGetSymbolAddress((void**)&p_xtl,  g_xtlo);

    static bool attr_set = false;
    if (!attr_set) {
        cudaFuncSetAttribute(gemm_hmma_kernel, cudaFuncAttributeMaxDynamicSharedMemorySize, 65536);
        attr_set = true;
    }

    // 1. spatial means + adjusted bias
    mean_kernel<<<B * DIMC, 256>>>(x, p_mean);
    bias_kernel<<<(B * 512 + 255) / 256, 256>>>(w_fc1, b_fc1, w_fcv, b_fcv, scaler, B);
    // 2. weight split (fc1/fcv), input transpose+split
    convw_kernel<<<512, 256>>>(w_fc1, w_fcv);
    {
        dim3 g(SPAT / 32, DIMC / 32, B);
        convx_kernel<<<g, dim3(32, 8)>>>(x);
    }
    // 3. fused fc1+fcv tensor-core GEMM (gap correction folded into bias)
    {
        dim3 grid(SPAT / 128, 512 / 128, B);
        gemm_hmma_kernel<<<grid, 256, 65536>>>(p_w1h, p_w1l, p_xth, p_xtl, p_bb, p_xv, 512, 1);
    }
    // 4. clustering; emits sim/mstar + y = W2.outm (exact fp32)
    cluster_kernel<<<B * 32, 256>>>(off_w1, off_b1, off_w2, off_b2, alpha, beta, w_fc2);
    // 5. combine -> final output (algebraic replacement of fc2 GEMM)
    {
        dim3 grid(8, 4, B);
        combine_kernel<<<grid, 256>>>(b_fc2, out);
    }
}